// round 5
// baseline (speedup 1.0000x reference)
#include <cuda_runtime.h>

// Problem constants
#define NB    8
#define NH    16
#define HDIM  64
#define NDIMS 1024
#define CTXL  4096
#define EFFS  16   // eff = min(ctx, HEAD) = 16 (faithful to source bug)

// Scratch (allocation-free rule: __device__ globals)
__device__ __align__(16) float g_iter1[NB * NH * EFFS * HDIM];
__device__ __align__(16) float g_iter2[NB * NH * EFFS * HDIM];
__device__ float g_diffsum;

// ---------------------------------------------------------------------------
// Kernel 1: fill entire output with ob (rows s<16 get overwritten by proj).
// Also resets the diff accumulator for this replay.
// grid = 32768 blocks x 256 threads, one float4 per thread.
// ---------------------------------------------------------------------------
__global__ void __launch_bounds__(256) fill_kernel(float4* __restrict__ out,
                                                   const float4* __restrict__ ob4) {
    unsigned i = blockIdx.x * 256u + threadIdx.x;
    if (i == 0) g_diffsum = 0.0f;
    // element col = (4*i) & 1023  ->  float4 col = i & 255 = threadIdx.x
    out[i] = ob4[threadIdx.x];
}

// ---------------------------------------------------------------------------
// Kernel 2: full per-(b,h) attention pipeline. 128 blocks (b*16+h), 256 thr.
// Computes LN(x) rows, q/k/v head projections, kn/vi, 3 unrolled iterations,
// stores iter1/iter2 to scratch, atomicAdds |iter1-iter0| sum.
// ---------------------------------------------------------------------------
__global__ void __launch_bounds__(256) attn_kernel(
    const float* __restrict__ x,
    const float* __restrict__ qw, const float* __restrict__ qb,
    const float* __restrict__ kw,
    const float* __restrict__ vw, const float* __restrict__ vb,
    const float* __restrict__ lna, const float* __restrict__ lnb,
    const float* __restrict__ lnc, const float* __restrict__ lnd,
    const float* __restrict__ lqw, const float* __restrict__ lqb,
    const float* __restrict__ lkw, const float* __restrict__ lkb,
    const float* __restrict__ lvw, const float* __restrict__ lvb)
{
    const int b = blockIdx.x >> 4;
    const int h = blockIdx.x & 15;
    const int t = threadIdx.x;

    __shared__ float sm_m[16], sm_r[16];
    __shared__ float qt[16][65];
    __shared__ float kt[16][65];
    __shared__ float vt[16][65];
    __shared__ float kn[16][65];
    __shared__ float vi[16][65];
    __shared__ float qcur[16][65];
    __shared__ float qn[16][65];
    __shared__ float itprev[16][65];
    __shared__ float prob[16][16];
    __shared__ float rm[16], rr[16];
    __shared__ float redbuf[8];

    const float* xb = x + (size_t)b * CTXL * NDIMS;

    // ---- per-row LN stats over 1024 dims (shared by lna/lnb paths) ----
    {
        const int s = t >> 4, l16 = t & 15;
        const float4* xr4 = (const float4*)(xb + s * NDIMS);
        float sum = 0.f, sq = 0.f;
        for (int j = l16; j < 256; j += 16) {
            float4 v = xr4[j];
            sum += v.x + v.y + v.z + v.w;
            sq  += v.x*v.x + v.y*v.y + v.z*v.z + v.w*v.w;
        }
        #pragma unroll
        for (int o = 8; o; o >>= 1) {
            sum += __shfl_xor_sync(0xffffffffu, sum, o);
            sq  += __shfl_xor_sync(0xffffffffu, sq,  o);
        }
        if (l16 == 0) {
            float m   = sum * (1.f / 1024.f);
            float var = sq  * (1.f / 1024.f) - m * m;
            sm_m[s] = m;
            sm_r[s] = rsqrtf(var + 1e-5f);
        }
    }
    __syncthreads();

    const int d  = t & 63;     // head dim owned by this thread
    const int s0 = t >> 6;     // s = s0 + 4*r, r in 0..3
    const int hd = h * HDIM + d;

    // ---- q/k/v projections for this head: [16 x 1024] @ [1024 x 64] ----
    {
        float aq[4] = {0,0,0,0}, ak[4] = {0,0,0,0}, av[4] = {0,0,0,0};
        const float4* qw4 = (const float4*)(qw + (size_t)hd * NDIMS);
        const float4* kw4 = (const float4*)(kw + (size_t)hd * NDIMS);
        const float4* vw4 = (const float4*)(vw + (size_t)hd * NDIMS);
        const float4* la4 = (const float4*)lna;
        const float4* lb4 = (const float4*)lnb;
        float mloc[4], rloc[4];
        const float4* x4[4];
        #pragma unroll
        for (int r = 0; r < 4; r++) {
            int s = s0 + 4*r;
            mloc[r] = sm_m[s];
            rloc[r] = sm_r[s];
            x4[r]   = (const float4*)(xb + s * NDIMS);
        }
        for (int j = 0; j < 256; j++) {
            float4 wq = qw4[j], wk = kw4[j], wv = vw4[j];
            float4 la = la4[j], lb = lb4[j];
            #pragma unroll
            for (int r = 0; r < 4; r++) {
                float4 xv = x4[r][j];
                float c0 = (xv.x - mloc[r]) * rloc[r];
                float c1 = (xv.y - mloc[r]) * rloc[r];
                float c2 = (xv.z - mloc[r]) * rloc[r];
                float c3 = (xv.w - mloc[r]) * rloc[r];
                float a0 = c0*la.x, a1 = c1*la.y, a2 = c2*la.z, a3 = c3*la.w;
                float b0 = c0*lb.x, b1 = c1*lb.y, b2 = c2*lb.z, b3 = c3*lb.w;
                aq[r] += a0*wq.x + a1*wq.y + a2*wq.z + a3*wq.w;
                ak[r] += b0*wk.x + b1*wk.y + b2*wk.z + b3*wk.w;
                av[r] += b0*wv.x + b1*wv.y + b2*wv.z + b3*wv.w;
            }
        }
        float qbv = qb[hd], vbv = vb[hd];
        #pragma unroll
        for (int r = 0; r < 4; r++) {
            int s = s0 + 4*r;
            qt[s][d] = aq[r] + qbv;
            kt[s][d] = ak[r];          // k linear: bias=False
            vt[s][d] = av[r] + vbv;
        }
    }
    __syncthreads();

    // ---- kn = LN(k @ lkw.T + lkb, lnd),  vi = v @ lvw.T + lvb ----
    {
        float akn[4], avi[4];
        float lkbv = lkb[d], lvbv = lvb[d];
        #pragma unroll
        for (int r = 0; r < 4; r++) { akn[r] = lkbv; avi[r] = lvbv; }
        const float* lkr = lkw + d * 64;
        const float* lvr = lvw + d * 64;
        for (int e = 0; e < 64; e++) {
            float wk = lkr[e], wv = lvr[e];
            #pragma unroll
            for (int r = 0; r < 4; r++) {
                int s = s0 + 4*r;
                akn[r] += kt[s][e] * wk;
                avi[r] += vt[s][e] * wv;
            }
        }
        #pragma unroll
        for (int r = 0; r < 4; r++) { int s = s0 + 4*r; kn[s][d] = akn[r]; vi[s][d] = avi[r]; }
    }
    __syncthreads();
    {   // LN over the 64-dim kn rows
        const int s = t >> 4, l16 = t & 15;
        float v0 = kn[s][l16], v1 = kn[s][l16+16], v2 = kn[s][l16+32], v3 = kn[s][l16+48];
        float sum = v0+v1+v2+v3;
        float sq  = v0*v0 + v1*v1 + v2*v2 + v3*v3;
        #pragma unroll
        for (int o = 8; o; o >>= 1) {
            sum += __shfl_xor_sync(0xffffffffu, sum, o);
            sq  += __shfl_xor_sync(0xffffffffu, sq,  o);
        }
        if (l16 == 0) {
            float m = sum * (1.f/64.f);
            float var = sq * (1.f/64.f) - m*m;
            rm[s] = m; rr[s] = rsqrtf(var + 1e-5f);
        }
    }
    __syncthreads();
    {
        float lndd = lnd[d];
        #pragma unroll
        for (int r = 0; r < 4; r++) {
            int s = s0 + 4*r;
            kn[s][d] = (kn[s][d] - rm[s]) * rr[s] * lndd;
            qcur[s][d] = qt[s][d];
        }
    }
    __syncthreads();

    // ---- 3 unrolled iterations ----
    float diffacc = 0.f;
    const float lqbv = lqb[d];
    const float lncd = lnc[d];
    for (int it = 0; it < 3; it++) {
        // qn_pre = qcur @ lqw.T + lqb
        {
            float aq[4];
            #pragma unroll
            for (int r = 0; r < 4; r++) aq[r] = lqbv;
            const float* lqr = lqw + d * 64;
            for (int e = 0; e < 64; e++) {
                float w = lqr[e];
                #pragma unroll
                for (int r = 0; r < 4; r++) aq[r] += qcur[s0 + 4*r][e] * w;
            }
            #pragma unroll
            for (int r = 0; r < 4; r++) qn[s0 + 4*r][d] = aq[r];
        }
        __syncthreads();
        {   // LN stats over 64
            const int s = t >> 4, l16 = t & 15;
            float v0 = qn[s][l16], v1 = qn[s][l16+16], v2 = qn[s][l16+32], v3 = qn[s][l16+48];
            float sum = v0+v1+v2+v3;
            float sq  = v0*v0 + v1*v1 + v2*v2 + v3*v3;
            #pragma unroll
            for (int o = 8; o; o >>= 1) {
                sum += __shfl_xor_sync(0xffffffffu, sum, o);
                sq  += __shfl_xor_sync(0xffffffffu, sq,  o);
            }
            if (l16 == 0) {
                float m = sum * (1.f/64.f);
                float var = sq * (1.f/64.f) - m*m;
                rm[s] = m; rr[s] = rsqrtf(var + 1e-5f);
            }
        }
        __syncthreads();
        {
            #pragma unroll
            for (int r = 0; r < 4; r++) {
                int s = s0 + 4*r;
                qn[s][d] = (qn[s][d] - rm[s]) * rr[s] * lncd;
            }
        }
        __syncthreads();
        // logits (16x16) + softmax
        {
            const int s = t >> 4, u = t & 15;
            float l = 0.f;
            #pragma unroll 8
            for (int e = 0; e < 64; e++) l += qn[s][e] * kn[u][e];
            l *= 0.125f;  // 1/sqrt(64)
            float mx = l;
            #pragma unroll
            for (int o = 8; o; o >>= 1) mx = fmaxf(mx, __shfl_xor_sync(0xffffffffu, mx, o));
            float ex = expf(l - mx);
            float sme = ex;
            #pragma unroll
            for (int o = 8; o; o >>= 1) sme += __shfl_xor_sync(0xffffffffu, sme, o);
            prob[s][u] = ex / sme;
        }
        __syncthreads();
        // attn = prob @ vi
        float at[4];
        #pragma unroll
        for (int r = 0; r < 4; r++) {
            int s = s0 + 4*r;
            float a = 0.f;
            #pragma unroll
            for (int u = 0; u < 16; u++) a += prob[s][u] * vi[u][d];
            at[r] = a;
        }
        // iteration bookkeeping
        if (it == 0) {
            #pragma unroll
            for (int r = 0; r < 4; r++) {
                int s = s0 + 4*r;
                itprev[s][d] = at[r];
                qcur[s][d]  += at[r];
            }
        } else if (it == 1) {
            #pragma unroll
            for (int r = 0; r < 4; r++) {
                int s = s0 + 4*r;
                diffacc += fabsf(at[r] - itprev[s][d]);
                qcur[s][d] += at[r];
                g_iter1[((size_t)blockIdx.x * 16 + s) * 64 + d] = at[r];
            }
        } else {
            #pragma unroll
            for (int r = 0; r < 4; r++) {
                int s = s0 + 4*r;
                g_iter2[((size_t)blockIdx.x * 16 + s) * 64 + d] = at[r];
            }
        }
        __syncthreads();
    }

    // block-reduce diffacc, one atomic per block
    #pragma unroll
    for (int o = 16; o; o >>= 1) diffacc += __shfl_xor_sync(0xffffffffu, diffacc, o);
    if ((t & 31) == 0) redbuf[t >> 5] = diffacc;
    __syncthreads();
    if (t < 8) {
        float v = redbuf[t];
        #pragma unroll
        for (int o = 4; o; o >>= 1) v += __shfl_xor_sync(0xffu, v, o);
        if (t == 0) atomicAdd(&g_diffsum, v);
    }
}

// ---------------------------------------------------------------------------
// Kernel 3: output projection for the 128 active rows.
// 128 blocks: (b, col-tile of 64). Selects iter1 vs iter2 via the diff test.
// ---------------------------------------------------------------------------
__global__ void __launch_bounds__(256) proj_kernel(
    const float* __restrict__ ow, const float* __restrict__ ob,
    float* __restrict__ out)
{
    const int b  = blockIdx.x >> 4;
    const int ct = blockIdx.x & 15;
    const int t  = threadIdx.x;

    float diff = g_diffsum * (1.0f / 33554432.0f);   // mean over full [8,16,4096,64]
    // brk = diff < THRESH + FACTOR*diff (it>0 satisfied at it=1)
    const float* A = (diff < (0.01f + 0.1f * diff)) ? g_iter1 : g_iter2;

    const int c  = ct * 64 + (t & 63);
    const int s0 = t >> 6;
    float acc[4] = {0.f, 0.f, 0.f, 0.f};
    const float4* owr4 = (const float4*)(ow + (size_t)c * NDIMS);

    for (int h = 0; h < 16; h++) {
        const float* Ab = A + (size_t)((b * 16 + h) * 16) * 64;
        #pragma unroll 4
        for (int d4 = 0; d4 < 16; d4++) {
            float4 w = owr4[h * 16 + d4];
            #pragma unroll
            for (int r = 0; r < 4; r++) {
                const float4 a = *(const float4*)(Ab + (s0 + 4*r) * 64 + d4 * 4);
                acc[r] += a.x*w.x + a.y*w.y + a.z*w.z + a.w*w.w;
            }
        }
    }
    float obv = ob[c];
    #pragma unroll
    for (int r = 0; r < 4; r++) {
        int s = s0 + 4*r;
        out[((size_t)b * CTXL + s) * NDIMS + c] = acc[r] + obv;
    }
}

// ---------------------------------------------------------------------------
extern "C" void kernel_launch(void* const* d_in, const int* in_sizes, int n_in,
                              void* d_out, int out_size) {
    const float* x   = (const float*)d_in[0];
    const float* qw  = (const float*)d_in[1];
    const float* qb  = (const float*)d_in[2];
    const float* kw  = (const float*)d_in[3];
    const float* vw  = (const float*)d_in[4];
    const float* vb  = (const float*)d_in[5];
    const float* ow  = (const float*)d_in[6];
    const float* ob  = (const float*)d_in[7];
    const float* lna = (const float*)d_in[8];
    const float* lnb = (const float*)d_in[9];
    const float* lnc = (const float*)d_in[10];
    const float* lnd = (const float*)d_in[11];
    const float* lqw = (const float*)d_in[12];
    const float* lqb = (const float*)d_in[13];
    const float* lkw = (const float*)d_in[14];
    const float* lkb = (const float*)d_in[15];
    const float* lvw = (const float*)d_in[16];
    const float* lvb = (const float*)d_in[17];
    float* out = (float*)d_out;

    // 1) broadcast ob into all rows (s>=16 is the final value there) + reset diff
    fill_kernel<<<(NB * CTXL * NDIMS / 4) / 256, 256>>>((float4*)out, (const float4*)ob);
    // 2) attention on the 128 active rows
    attn_kernel<<<NB * NH, 256>>>(x, qw, qb, kw, vw, vb,
                                  lna, lnb, lnc, lnd,
                                  lqw, lqb, lkw, lkb, lvw, lvb);
    // 3) output projection overwrites rows s<16
    proj_kernel<<<NB * NH, 256>>>(ow, ob, out);
}

// round 6
// speedup vs baseline: 2.2267x; 2.2267x over previous
#include <cuda_runtime.h>

#define NB    8
#define NH    16
#define HDIM  64
#define NDIMS 1024
#define CTXL  4096

// Scratch (__device__ globals: allocation-free rule)
__device__ __align__(16) float g_xa[128 * 1024];
__device__ __align__(16) float g_xb[128 * 1024];
__device__ __align__(16) float g_q [128 * 1024];
__device__ __align__(16) float g_k [128 * 1024];
__device__ __align__(16) float g_v [128 * 1024];
__device__ __align__(16) float g_A1[128 * 1024];
__device__ __align__(16) float g_A2[128 * 1024];
__device__ float g_diffsum;

// ---------------------------------------------------------------------------
// Kernel 1: persistent grid-stride fill of the output with ob; reset diffsum.
// ---------------------------------------------------------------------------
__global__ void __launch_bounds__(256) fill_kernel(float4* __restrict__ out,
                                                   const float4* __restrict__ ob4) {
    if (blockIdx.x == 0 && threadIdx.x == 0) g_diffsum = 0.0f;
    const float4 v = ob4[threadIdx.x];          // col = (4i)&1023 -> i&255 = tid
    const unsigned total  = (unsigned)(NB * CTXL * NDIMS / 4);   // 8,388,608
    const unsigned stride = gridDim.x * 256u;
    for (unsigned i = blockIdx.x * 256u + threadIdx.x; i < total; i += stride)
        out[i] = v;
}

// ---------------------------------------------------------------------------
// Kernel 2: LayerNorm of the 128 active rows -> g_xa (lna) and g_xb (lnb).
// ---------------------------------------------------------------------------
__global__ void __launch_bounds__(256) ln_kernel(const float* __restrict__ x,
                                                 const float* __restrict__ lna,
                                                 const float* __restrict__ lnb) {
    const int row = blockIdx.x;                 // 0..127 = b*16+s
    const int b = row >> 4, s = row & 15;
    const int t = threadIdx.x;
    const float4* xr = (const float4*)(x + ((size_t)b * CTXL + s) * NDIMS);
    float4 v = xr[t];
    float sum = v.x + v.y + v.z + v.w;
    float sq  = v.x*v.x + v.y*v.y + v.z*v.z + v.w*v.w;
    #pragma unroll
    for (int o = 16; o; o >>= 1) {
        sum += __shfl_xor_sync(0xffffffffu, sum, o);
        sq  += __shfl_xor_sync(0xffffffffu, sq,  o);
    }
    __shared__ float s1[8], s2[8], sm_m, sm_r;
    if ((t & 31) == 0) { s1[t >> 5] = sum; s2[t >> 5] = sq; }
    __syncthreads();
    if (t == 0) {
        float a = 0.f, q = 0.f;
        #pragma unroll
        for (int i = 0; i < 8; i++) { a += s1[i]; q += s2[i]; }
        float m   = a * (1.f / 1024.f);
        float var = q * (1.f / 1024.f) - m * m;
        sm_m = m; sm_r = rsqrtf(var + 1e-5f);
    }
    __syncthreads();
    const float m = sm_m, rs = sm_r;
    float4 la = ((const float4*)lna)[t];
    float4 lb = ((const float4*)lnb)[t];
    float4 xa, xb;
    float c0 = (v.x - m) * rs, c1 = (v.y - m) * rs, c2 = (v.z - m) * rs, c3 = (v.w - m) * rs;
    xa.x = c0 * la.x; xa.y = c1 * la.y; xa.z = c2 * la.z; xa.w = c3 * la.w;
    xb.x = c0 * lb.x; xb.y = c1 * lb.y; xb.z = c2 * lb.z; xb.w = c3 * lb.w;
    ((float4*)g_xa)[row * 256 + t] = xa;
    ((float4*)g_xb)[row * 256 + t] = xb;
}

// ---------------------------------------------------------------------------
// Kernel 3: q/k/v projections as coalesced tiled GEMM.
// grid (32 colTiles, 4 rowTiles, 3 matrices), 256 thr, 32x32 output tile.
// out[r][c] = sum_k IN[r][k] * W[c][k] (+bias)
// ---------------------------------------------------------------------------
__global__ void __launch_bounds__(256) qkv_gemm(
    const float* __restrict__ qw, const float* __restrict__ qb,
    const float* __restrict__ kw,
    const float* __restrict__ vw, const float* __restrict__ vb) {
    const int mat = blockIdx.z;
    const float* IN   = (mat == 0) ? g_xa : g_xb;
    const float* W    = (mat == 0) ? qw : (mat == 1) ? kw : vw;
    const float* bias = (mat == 0) ? qb : (mat == 1) ? (const float*)0 : vb;
    float* OUT        = (mat == 0) ? g_q : (mat == 1) ? g_k : g_v;

    const int c0 = blockIdx.x * 32, r0 = blockIdx.y * 32;
    const int t  = threadIdx.x;
    __shared__ float Xs[32][36];   // [row][k]
    __shared__ float Ws[32][36];   // [k][col] (transposed)
    const int cx = (t & 15) * 2;          // 2 cols
    const int ry = (t >> 4) * 2;          // 2 rows
    const int lr = t >> 3, kq = (t & 7) * 4;   // load mapping
    float a00 = 0.f, a01 = 0.f, a10 = 0.f, a11 = 0.f;

    for (int k0 = 0; k0 < 1024; k0 += 32) {
        float4 xv = *(const float4*)(IN + (size_t)(r0 + lr) * 1024 + k0 + kq);
        float4 wv = *(const float4*)(W  + (size_t)(c0 + lr) * 1024 + k0 + kq);
        __syncthreads();
        *(float4*)&Xs[lr][kq] = xv;
        Ws[kq + 0][lr] = wv.x; Ws[kq + 1][lr] = wv.y;
        Ws[kq + 2][lr] = wv.z; Ws[kq + 3][lr] = wv.w;
        __syncthreads();
        #pragma unroll
        for (int k = 0; k < 32; k++) {
            float x0 = Xs[ry][k], x1 = Xs[ry + 1][k];
            float2 w = *(float2*)&Ws[k][cx];
            a00 += x0 * w.x; a01 += x0 * w.y;
            a10 += x1 * w.x; a11 += x1 * w.y;
        }
    }
    float b0 = 0.f, b1 = 0.f;
    if (bias) { b0 = bias[c0 + cx]; b1 = bias[c0 + cx + 1]; }
    OUT[(size_t)(r0 + ry)     * 1024 + c0 + cx]     = a00 + b0;
    OUT[(size_t)(r0 + ry)     * 1024 + c0 + cx + 1] = a01 + b1;
    OUT[(size_t)(r0 + ry + 1) * 1024 + c0 + cx]     = a10 + b0;
    OUT[(size_t)(r0 + ry + 1) * 1024 + c0 + cx + 1] = a11 + b1;
}

// ---------------------------------------------------------------------------
// Kernel 4: per-(b,h) attention iterations. Weights staged in smem (padded,
// conflict-free); q/k/v tiles read coalesced from g_q/g_k/g_v.
// Dynamic smem (~80KB).
// ---------------------------------------------------------------------------
__global__ void __launch_bounds__(256) attn_kernel(
    const float* __restrict__ lnc, const float* __restrict__ lnd,
    const float* __restrict__ lqw, const float* __restrict__ lqb,
    const float* __restrict__ lkw, const float* __restrict__ lkb,
    const float* __restrict__ lvw, const float* __restrict__ lvb) {
    extern __shared__ float sm[];
    float (*wq)[65] = (float(*)[65])sm;                  // 64x65
    float (*wk)[65] = (float(*)[65])(sm + 64 * 65);
    float (*wv)[65] = (float(*)[65])(sm + 2 * 64 * 65);
    float (*kt)[65] = (float(*)[65])(sm + 3 * 64 * 65);  // 16x65 each below
    float (*vt)[65] = kt + 16;
    float (*kn)[65] = vt + 16;
    float (*vi)[65] = kn + 16;
    float (*qc)[65] = vi + 16;
    float (*qn)[65] = qc + 16;
    float (*ip)[65] = qn + 16;
    float (*prob)[16] = (float(*)[16])(ip + 16);         // 16x16
    float* rm  = (float*)(prob + 16);                    // 16
    float* rr  = rm + 16;                                // 16
    float* red = rr + 16;                                // 8

    const int t = threadIdx.x;
    const int b = blockIdx.x >> 4, h = blockIdx.x & 15;

    // stage 64x64 weights (coalesced float4 loads, scalar smem stores)
    {
        const int rw = t >> 4, col = (t & 15) * 4;
        #pragma unroll
        for (int p = 0; p < 4; p++) {
            int row = p * 16 + rw;
            float4 a = *(const float4*)(lqw + row * 64 + col);
            wq[row][col] = a.x; wq[row][col+1] = a.y; wq[row][col+2] = a.z; wq[row][col+3] = a.w;
            float4 c = *(const float4*)(lkw + row * 64 + col);
            wk[row][col] = c.x; wk[row][col+1] = c.y; wk[row][col+2] = c.z; wk[row][col+3] = c.w;
            float4 e = *(const float4*)(lvw + row * 64 + col);
            wv[row][col] = e.x; wv[row][col+1] = e.y; wv[row][col+2] = e.z; wv[row][col+3] = e.w;
        }
    }
    const int d = t & 63, s0 = t >> 6;
    const size_t base = (size_t)(b * 16) * 1024 + h * 64 + d;
    #pragma unroll
    for (int r = 0; r < 4; r++) {
        int s = s0 + 4 * r;
        qc[s][d] = g_q[base + (size_t)s * 1024];
        kt[s][d] = g_k[base + (size_t)s * 1024];
        vt[s][d] = g_v[base + (size_t)s * 1024];
    }
    __syncthreads();

    // kn_pre = k @ lkw.T + lkb, vi = v @ lvw.T + lvb
    {
        float akn[4], avi[4];
        const float bk = lkb[d], bv = lvb[d];
        #pragma unroll
        for (int r = 0; r < 4; r++) { akn[r] = bk; avi[r] = bv; }
        for (int e = 0; e < 64; e++) {
            float wke = wk[d][e], wve = wv[d][e];
            #pragma unroll
            for (int r = 0; r < 4; r++) {
                int s = s0 + 4 * r;
                akn[r] += kt[s][e] * wke;
                avi[r] += vt[s][e] * wve;
            }
        }
        #pragma unroll
        for (int r = 0; r < 4; r++) { int s = s0 + 4 * r; kn[s][d] = akn[r]; vi[s][d] = avi[r]; }
    }
    __syncthreads();
    {   // LN over 64-dim kn rows
        const int s = t >> 4, l16 = t & 15;
        float v0 = kn[s][l16], v1 = kn[s][l16+16], v2 = kn[s][l16+32], v3 = kn[s][l16+48];
        float sum = v0+v1+v2+v3, sq = v0*v0+v1*v1+v2*v2+v3*v3;
        #pragma unroll
        for (int o = 8; o; o >>= 1) {
            sum += __shfl_xor_sync(0xffffffffu, sum, o);
            sq  += __shfl_xor_sync(0xffffffffu, sq,  o);
        }
        if (l16 == 0) {
            float m = sum * (1.f/64.f), var = sq * (1.f/64.f) - m*m;
            rm[s] = m; rr[s] = rsqrtf(var + 1e-5f);
        }
    }
    __syncthreads();
    {
        const float lndd = lnd[d];
        #pragma unroll
        for (int r = 0; r < 4; r++) {
            int s = s0 + 4 * r;
            kn[s][d] = (kn[s][d] - rm[s]) * rr[s] * lndd;
        }
    }
    __syncthreads();

    // 3 unrolled iterations
    float diffacc = 0.f;
    const float lqbv = lqb[d], lncd = lnc[d];
    for (int it = 0; it < 3; it++) {
        {   // qn_pre = qc @ lqw.T + lqb
            float aq[4];
            #pragma unroll
            for (int r = 0; r < 4; r++) aq[r] = lqbv;
            for (int e = 0; e < 64; e++) {
                float w = wq[d][e];
                #pragma unroll
                for (int r = 0; r < 4; r++) aq[r] += qc[s0 + 4*r][e] * w;
            }
            #pragma unroll
            for (int r = 0; r < 4; r++) qn[s0 + 4*r][d] = aq[r];
        }
        __syncthreads();
        {   // LN stats over 64
            const int s = t >> 4, l16 = t & 15;
            float v0 = qn[s][l16], v1 = qn[s][l16+16], v2 = qn[s][l16+32], v3 = qn[s][l16+48];
            float sum = v0+v1+v2+v3, sq = v0*v0+v1*v1+v2*v2+v3*v3;
            #pragma unroll
            for (int o = 8; o; o >>= 1) {
                sum += __shfl_xor_sync(0xffffffffu, sum, o);
                sq  += __shfl_xor_sync(0xffffffffu, sq,  o);
            }
            if (l16 == 0) {
                float m = sum * (1.f/64.f), var = sq * (1.f/64.f) - m*m;
                rm[s] = m; rr[s] = rsqrtf(var + 1e-5f);
            }
        }
        __syncthreads();
        {
            #pragma unroll
            for (int r = 0; r < 4; r++) {
                int s = s0 + 4 * r;
                qn[s][d] = (qn[s][d] - rm[s]) * rr[s] * lncd;
            }
        }
        __syncthreads();
        {   // logits 16x16 + softmax
            const int s = t >> 4, u = t & 15;
            float l = 0.f;
            #pragma unroll 8
            for (int e = 0; e < 64; e++) l += qn[s][e] * kn[u][e];
            l *= 0.125f;
            float mx = l;
            #pragma unroll
            for (int o = 8; o; o >>= 1) mx = fmaxf(mx, __shfl_xor_sync(0xffffffffu, mx, o));
            float ex = expf(l - mx);
            float sme = ex;
            #pragma unroll
            for (int o = 8; o; o >>= 1) sme += __shfl_xor_sync(0xffffffffu, sme, o);
            prob[s][u] = ex / sme;
        }
        __syncthreads();
        float at[4];
        #pragma unroll
        for (int r = 0; r < 4; r++) {
            int s = s0 + 4 * r;
            float a = 0.f;
            #pragma unroll
            for (int u = 0; u < 16; u++) a += prob[s][u] * vi[u][d];
            at[r] = a;
        }
        if (it == 0) {
            #pragma unroll
            for (int r = 0; r < 4; r++) {
                int s = s0 + 4 * r;
                ip[s][d] = at[r];
                qc[s][d] += at[r];
            }
        } else if (it == 1) {
            #pragma unroll
            for (int r = 0; r < 4; r++) {
                int s = s0 + 4 * r;
                diffacc += fabsf(at[r] - ip[s][d]);
                qc[s][d] += at[r];
                g_A1[base + (size_t)s * 1024] = at[r];
            }
        } else {
            #pragma unroll
            for (int r = 0; r < 4; r++) {
                int s = s0 + 4 * r;
                g_A2[base + (size_t)s * 1024] = at[r];
            }
        }
        __syncthreads();
    }

    // block reduce + one atomic
    #pragma unroll
    for (int o = 16; o; o >>= 1) diffacc += __shfl_xor_sync(0xffffffffu, diffacc, o);
    if ((t & 31) == 0) red[t >> 5] = diffacc;
    __syncthreads();
    if (t < 8) {
        float v = red[t];
        #pragma unroll
        for (int o = 4; o; o >>= 1) v += __shfl_xor_sync(0xffu, v, o);
        if (t == 0) atomicAdd(&g_diffsum, v);
    }
}

// ---------------------------------------------------------------------------
// Kernel 5: output projection, same tiling as qkv_gemm; selects iter1/iter2;
// scatters rows to out[(b*CTX + s)*1024 + c] and adds ob.
// ---------------------------------------------------------------------------
__global__ void __launch_bounds__(256) proj_gemm(
    const float* __restrict__ ow, const float* __restrict__ ob,
    float* __restrict__ out) {
    const float diff = g_diffsum * (1.0f / 33554432.0f);
    const float* IN = (diff < (0.01f + 0.1f * diff)) ? g_A1 : g_A2;

    const int c0 = blockIdx.x * 32, r0 = blockIdx.y * 32;
    const int t  = threadIdx.x;
    __shared__ float Xs[32][36];
    __shared__ float Ws[32][36];
    const int cx = (t & 15) * 2;
    const int ry = (t >> 4) * 2;
    const int lr = t >> 3, kq = (t & 7) * 4;
    float a00 = 0.f, a01 = 0.f, a10 = 0.f, a11 = 0.f;

    for (int k0 = 0; k0 < 1024; k0 += 32) {
        float4 xv = *(const float4*)(IN + (size_t)(r0 + lr) * 1024 + k0 + kq);
        float4 wv = *(const float4*)(ow + (size_t)(c0 + lr) * 1024 + k0 + kq);
        __syncthreads();
        *(float4*)&Xs[lr][kq] = xv;
        Ws[kq + 0][lr] = wv.x; Ws[kq + 1][lr] = wv.y;
        Ws[kq + 2][lr] = wv.z; Ws[kq + 3][lr] = wv.w;
        __syncthreads();
        #pragma unroll
        for (int k = 0; k < 32; k++) {
            float x0 = Xs[ry][k], x1 = Xs[ry + 1][k];
            float2 w = *(float2*)&Ws[k][cx];
            a00 += x0 * w.x; a01 += x0 * w.y;
            a10 += x1 * w.x; a11 += x1 * w.y;
        }
    }
    const float b0 = ob[c0 + cx], b1 = ob[c0 + cx + 1];
    const int g0 = r0 + ry, g1 = g0 + 1;
    size_t o0 = ((size_t)(g0 >> 4) * CTXL + (g0 & 15)) * 1024 + c0 + cx;
    size_t o1 = ((size_t)(g1 >> 4) * CTXL + (g1 & 15)) * 1024 + c0 + cx;
    out[o0]     = a00 + b0;
    out[o0 + 1] = a01 + b1;
    out[o1]     = a10 + b0;
    out[o1 + 1] = a11 + b1;
}

// ---------------------------------------------------------------------------
extern "C" void kernel_launch(void* const* d_in, const int* in_sizes, int n_in,
                              void* d_out, int out_size) {
    const float* x   = (const float*)d_in[0];
    const float* qw  = (const float*)d_in[1];
    const float* qb  = (const float*)d_in[2];
    const float* kw  = (const float*)d_in[3];
    const float* vw  = (const float*)d_in[4];
    const float* vb  = (const float*)d_in[5];
    const float* ow  = (const float*)d_in[6];
    const float* ob  = (const float*)d_in[7];
    const float* lna = (const float*)d_in[8];
    const float* lnb = (const float*)d_in[9];
    const float* lnc = (const float*)d_in[10];
    const float* lnd = (const float*)d_in[11];
    const float* lqw = (const float*)d_in[12];
    const float* lqb = (const float*)d_in[13];
    const float* lkw = (const float*)d_in[14];
    const float* lkb = (const float*)d_in[15];
    const float* lvw = (const float*)d_in[16];
    const float* lvb = (const float*)d_in[17];
    float* out = (float*)d_out;

    // dynamic smem for attn_kernel: 3*64*65 + 7*16*65 + 256 + 40 floats
    const int attn_smem = (3 * 64 * 65 + 7 * 16 * 65 + 256 + 40) * 4;
    cudaFuncSetAttribute(attn_kernel, cudaFuncAttributeMaxDynamicSharedMemorySize,
                         attn_smem);

    fill_kernel<<<2048, 256>>>((float4*)out, (const float4*)ob);
    ln_kernel<<<128, 256>>>(x, lna, lnb);
    qkv_gemm<<<dim3(32, 4, 3), 256>>>(qw, qb, kw, vw, vb);
    attn_kernel<<<128, 256, attn_smem>>>(lnc, lnd, lqw, lqb, lkw, lkb, lvw, lvb);
    proj_gemm<<<dim3(32, 4), 256>>>(ow, ob, out);
}

// round 7
// speedup vs baseline: 2.5788x; 1.1581x over previous
#include <cuda_runtime.h>

#define NB    8
#define NH    16
#define HDIM  64
#define NDIMS 1024
#define CTXL  4096

// Scratch (__device__ globals: allocation-free rule)
__device__ __align__(16) float g_xa[128 * 1024];
__device__ __align__(16) float g_xb[128 * 1024];
__device__ __align__(16) float g_q [128 * 1024];
__device__ __align__(16) float g_k [128 * 1024];
__device__ __align__(16) float g_v [128 * 1024];
__device__ __align__(16) float g_A1[128 * 1024];
__device__ __align__(16) float g_A2[128 * 1024];
__device__ float g_diffsum;

// ---------------------------------------------------------------------------
// tf32 helpers
// ---------------------------------------------------------------------------
__device__ __forceinline__ unsigned f2tf(float f) {
    unsigned r;
    asm("cvt.rna.tf32.f32 %0, %1;" : "=r"(r) : "f"(f));
    return r;
}
__device__ __forceinline__ void mma_tf32(float* c, unsigned a0, unsigned a1,
                                         unsigned a2, unsigned a3,
                                         unsigned b0, unsigned b1) {
    asm("mma.sync.aligned.m16n8k8.row.col.f32.tf32.tf32.f32 "
        "{%0,%1,%2,%3},{%4,%5,%6,%7},{%8,%9},{%0,%1,%2,%3};"
        : "+f"(c[0]), "+f"(c[1]), "+f"(c[2]), "+f"(c[3])
        : "r"(a0), "r"(a1), "r"(a2), "r"(a3), "r"(b0), "r"(b1));
}

// ---------------------------------------------------------------------------
// Kernel 1: LayerNorm of 128 active rows -> g_xa (lna), g_xb (lnb); reset diff.
// ---------------------------------------------------------------------------
__global__ void __launch_bounds__(256) ln_kernel(const float* __restrict__ x,
                                                 const float* __restrict__ lna,
                                                 const float* __restrict__ lnb) {
    if (blockIdx.x == 0 && threadIdx.x == 0) g_diffsum = 0.0f;
    const int row = blockIdx.x;                 // 0..127 = b*16+s
    const int b = row >> 4, s = row & 15;
    const int t = threadIdx.x;
    const float4* xr = (const float4*)(x + ((size_t)b * CTXL + s) * NDIMS);
    float4 v = xr[t];
    float sum = v.x + v.y + v.z + v.w;
    float sq  = v.x*v.x + v.y*v.y + v.z*v.z + v.w*v.w;
    #pragma unroll
    for (int o = 16; o; o >>= 1) {
        sum += __shfl_xor_sync(0xffffffffu, sum, o);
        sq  += __shfl_xor_sync(0xffffffffu, sq,  o);
    }
    __shared__ float s1[8], s2[8], sm_m, sm_r;
    if ((t & 31) == 0) { s1[t >> 5] = sum; s2[t >> 5] = sq; }
    __syncthreads();
    if (t == 0) {
        float a = 0.f, q = 0.f;
        #pragma unroll
        for (int i = 0; i < 8; i++) { a += s1[i]; q += s2[i]; }
        float m   = a * (1.f / 1024.f);
        float var = q * (1.f / 1024.f) - m * m;
        sm_m = m; sm_r = rsqrtf(var + 1e-5f);
    }
    __syncthreads();
    const float m = sm_m, rs = sm_r;
    float4 la = ((const float4*)lna)[t];
    float4 lb = ((const float4*)lnb)[t];
    float4 xa, xb;
    float c0 = (v.x - m) * rs, c1 = (v.y - m) * rs, c2 = (v.z - m) * rs, c3 = (v.w - m) * rs;
    xa.x = c0 * la.x; xa.y = c1 * la.y; xa.z = c2 * la.z; xa.w = c3 * la.w;
    xb.x = c0 * lb.x; xb.y = c1 * lb.y; xb.z = c2 * lb.z; xb.w = c3 * lb.w;
    ((float4*)g_xa)[row * 256 + t] = xa;
    ((float4*)g_xb)[row * 256 + t] = xb;
}

// ---------------------------------------------------------------------------
// Kernel 2: q/k/v projections as tf32 tensor-core GEMM + first half of fill.
// GEMM blocks 0..191: mat = bid/64, 32x64 tile. Fill blocks 192..351.
// out[r][c] = sum_k IN[r][k] * W[c][k] (+bias)
// ---------------------------------------------------------------------------
__global__ void __launch_bounds__(256) qkv_tc(
    const float* __restrict__ qw, const float* __restrict__ qb,
    const float* __restrict__ kw,
    const float* __restrict__ vw, const float* __restrict__ vb,
    float4* __restrict__ out4, const float4* __restrict__ ob4) {
    const int t = threadIdx.x;
    const int bid = blockIdx.x;
    if (bid >= 192) {
        // fill first half of out: [0, 4194304) float4s
        const float4 v = ob4[t];               // i & 255 == t (stride mult of 256)
        const unsigned stride = 160u * 256u;
        for (unsigned i = (unsigned)(bid - 192) * 256u + t; i < 4194304u; i += stride)
            out4[i] = v;
        return;
    }
    const int mat = bid >> 6;                  // 64 blocks per matrix
    const int sub = bid & 63;
    const int r0 = (sub >> 4) * 32;
    const int c0 = (sub & 15) * 64;
    const float* IN   = (mat == 0) ? g_xa : g_xb;
    const float* W    = (mat == 0) ? qw : (mat == 1) ? kw : vw;
    const float* bias = (mat == 0) ? qb : (mat == 1) ? (const float*)0 : vb;
    float* OUT        = (mat == 0) ? g_q : (mat == 1) ? g_k : g_v;

    __shared__ float As[32][36];
    __shared__ float Ws[64][36];

    const int w = t >> 5, l = t & 31;
    const int mr  = (w >> 2) * 16;             // warp m offset {0,16}
    const int nc  = (w & 3) * 16;              // warp n offset {0,16,32,48}
    const int g   = l >> 2, tig = l & 3;
    const int lrow = t >> 3, lk = (t & 7) * 4; // staging map

    float acc[2][4] = {{0,0,0,0},{0,0,0,0}};

    for (int k0 = 0; k0 < 1024; k0 += 32) {
        float4 xa = *(const float4*)(IN + (size_t)(r0 + lrow) * 1024 + k0 + lk);
        float4 w0 = *(const float4*)(W  + (size_t)(c0 + lrow) * 1024 + k0 + lk);
        float4 w1 = *(const float4*)(W  + (size_t)(c0 + 32 + lrow) * 1024 + k0 + lk);
        __syncthreads();
        *(float4*)&As[lrow][lk]      = xa;
        *(float4*)&Ws[lrow][lk]      = w0;
        *(float4*)&Ws[32 + lrow][lk] = w1;
        __syncthreads();
        #pragma unroll
        for (int ks = 0; ks < 4; ks++) {
            const int kb = ks * 8;
            unsigned a0 = f2tf(As[mr + g][kb + tig]);
            unsigned a1 = f2tf(As[mr + g + 8][kb + tig]);
            unsigned a2 = f2tf(As[mr + g][kb + tig + 4]);
            unsigned a3 = f2tf(As[mr + g + 8][kb + tig + 4]);
            #pragma unroll
            for (int j = 0; j < 2; j++) {
                unsigned b0 = f2tf(Ws[nc + j * 8 + g][kb + tig]);
                unsigned b1 = f2tf(Ws[nc + j * 8 + g][kb + tig + 4]);
                mma_tf32(acc[j], a0, a1, a2, a3, b0, b1);
            }
        }
    }
    const int row0 = r0 + mr + g, row1 = row0 + 8;
    #pragma unroll
    for (int j = 0; j < 2; j++) {
        const int colb = c0 + nc + j * 8 + 2 * tig;
        float b0v = 0.f, b1v = 0.f;
        if (bias) { b0v = bias[colb]; b1v = bias[colb + 1]; }
        OUT[(size_t)row0 * 1024 + colb]     = acc[j][0] + b0v;
        OUT[(size_t)row0 * 1024 + colb + 1] = acc[j][1] + b1v;
        OUT[(size_t)row1 * 1024 + colb]     = acc[j][2] + b0v;
        OUT[(size_t)row1 * 1024 + colb + 1] = acc[j][3] + b1v;
    }
}

// ---------------------------------------------------------------------------
// Kernel 3: per-(b,h) attention iterations (blocks 0..127, fp32) + second half
// of fill (blocks 128..351). Dynamic smem ~80KB for attn blocks.
// ---------------------------------------------------------------------------
__global__ void __launch_bounds__(256) attn_kernel(
    const float* __restrict__ lnc, const float* __restrict__ lnd,
    const float* __restrict__ lqw, const float* __restrict__ lqb,
    const float* __restrict__ lkw, const float* __restrict__ lkb,
    const float* __restrict__ lvw, const float* __restrict__ lvb,
    float4* __restrict__ out4, const float4* __restrict__ ob4) {
    const int t = threadIdx.x;
    if (blockIdx.x >= 128) {
        // fill second half of out: [4194304, 8388608) float4s
        const float4 v = ob4[t];
        const unsigned stride = 224u * 256u;
        for (unsigned i = 4194304u + (unsigned)(blockIdx.x - 128) * 256u + t;
             i < 8388608u; i += stride)
            out4[i] = v;
        return;
    }
    extern __shared__ float sm[];
    float (*wq)[65] = (float(*)[65])sm;                  // 64x65
    float (*wk)[65] = (float(*)[65])(sm + 64 * 65);
    float (*wv)[65] = (float(*)[65])(sm + 2 * 64 * 65);
    float (*kt)[65] = (float(*)[65])(sm + 3 * 64 * 65);  // 16x65 each below
    float (*vt)[65] = kt + 16;
    float (*kn)[65] = vt + 16;
    float (*vi)[65] = kn + 16;
    float (*qc)[65] = vi + 16;
    float (*qn)[65] = qc + 16;
    float (*ip)[65] = qn + 16;
    float (*prob)[16] = (float(*)[16])(ip + 16);         // 16x16
    float* rm  = (float*)(prob + 16);                    // 16
    float* rr  = rm + 16;                                // 16
    float* red = rr + 16;                                // 8

    const int b = blockIdx.x >> 4, h = blockIdx.x & 15;

    // stage 64x64 weights (coalesced float4 loads, scalar smem stores)
    {
        const int rw = t >> 4, col = (t & 15) * 4;
        #pragma unroll
        for (int p = 0; p < 4; p++) {
            int row = p * 16 + rw;
            float4 a = *(const float4*)(lqw + row * 64 + col);
            wq[row][col] = a.x; wq[row][col+1] = a.y; wq[row][col+2] = a.z; wq[row][col+3] = a.w;
            float4 c = *(const float4*)(lkw + row * 64 + col);
            wk[row][col] = c.x; wk[row][col+1] = c.y; wk[row][col+2] = c.z; wk[row][col+3] = c.w;
            float4 e = *(const float4*)(lvw + row * 64 + col);
            wv[row][col] = e.x; wv[row][col+1] = e.y; wv[row][col+2] = e.z; wv[row][col+3] = e.w;
        }
    }
    const int d = t & 63, s0 = t >> 6;
    const size_t base = (size_t)(b * 16) * 1024 + h * 64 + d;
    #pragma unroll
    for (int r = 0; r < 4; r++) {
        int s = s0 + 4 * r;
        qc[s][d] = g_q[base + (size_t)s * 1024];
        kt[s][d] = g_k[base + (size_t)s * 1024];
        vt[s][d] = g_v[base + (size_t)s * 1024];
    }
    __syncthreads();

    // kn_pre = k @ lkw.T + lkb, vi = v @ lvw.T + lvb
    {
        float akn[4], avi[4];
        const float bk = lkb[d], bv = lvb[d];
        #pragma unroll
        for (int r = 0; r < 4; r++) { akn[r] = bk; avi[r] = bv; }
        for (int e = 0; e < 64; e++) {
            float wke = wk[d][e], wve = wv[d][e];
            #pragma unroll
            for (int r = 0; r < 4; r++) {
                int s = s0 + 4 * r;
                akn[r] += kt[s][e] * wke;
                avi[r] += vt[s][e] * wve;
            }
        }
        #pragma unroll
        for (int r = 0; r < 4; r++) { int s = s0 + 4 * r; kn[s][d] = akn[r]; vi[s][d] = avi[r]; }
    }
    __syncthreads();
    {   // LN over 64-dim kn rows
        const int s = t >> 4, l16 = t & 15;
        float v0 = kn[s][l16], v1 = kn[s][l16+16], v2 = kn[s][l16+32], v3 = kn[s][l16+48];
        float sum = v0+v1+v2+v3, sq = v0*v0+v1*v1+v2*v2+v3*v3;
        #pragma unroll
        for (int o = 8; o; o >>= 1) {
            sum += __shfl_xor_sync(0xffffffffu, sum, o);
            sq  += __shfl_xor_sync(0xffffffffu, sq,  o);
        }
        if (l16 == 0) {
            float m = sum * (1.f/64.f), var = sq * (1.f/64.f) - m*m;
            rm[s] = m; rr[s] = rsqrtf(var + 1e-5f);
        }
    }
    __syncthreads();
    {
        const float lndd = lnd[d];
        #pragma unroll
        for (int r = 0; r < 4; r++) {
            int s = s0 + 4 * r;
            kn[s][d] = (kn[s][d] - rm[s]) * rr[s] * lndd;
        }
    }
    __syncthreads();

    // 3 unrolled iterations
    float diffacc = 0.f;
    const float lqbv = lqb[d], lncd = lnc[d];
    for (int it = 0; it < 3; it++) {
        {   // qn_pre = qc @ lqw.T + lqb
            float aq[4];
            #pragma unroll
            for (int r = 0; r < 4; r++) aq[r] = lqbv;
            for (int e = 0; e < 64; e++) {
                float w = wq[d][e];
                #pragma unroll
                for (int r = 0; r < 4; r++) aq[r] += qc[s0 + 4*r][e] * w;
            }
            #pragma unroll
            for (int r = 0; r < 4; r++) qn[s0 + 4*r][d] = aq[r];
        }
        __syncthreads();
        {   // LN stats over 64
            const int s = t >> 4, l16 = t & 15;
            float v0 = qn[s][l16], v1 = qn[s][l16+16], v2 = qn[s][l16+32], v3 = qn[s][l16+48];
            float sum = v0+v1+v2+v3, sq = v0*v0+v1*v1+v2*v2+v3*v3;
            #pragma unroll
            for (int o = 8; o; o >>= 1) {
                sum += __shfl_xor_sync(0xffffffffu, sum, o);
                sq  += __shfl_xor_sync(0xffffffffu, sq,  o);
            }
            if (l16 == 0) {
                float m = sum * (1.f/64.f), var = sq * (1.f/64.f) - m*m;
                rm[s] = m; rr[s] = rsqrtf(var + 1e-5f);
            }
        }
        __syncthreads();
        {
            #pragma unroll
            for (int r = 0; r < 4; r++) {
                int s = s0 + 4 * r;
                qn[s][d] = (qn[s][d] - rm[s]) * rr[s] * lncd;
            }
        }
        __syncthreads();
        {   // logits 16x16 + softmax
            const int s = t >> 4, u = t & 15;
            float l = 0.f;
            #pragma unroll 8
            for (int e = 0; e < 64; e++) l += qn[s][e] * kn[u][e];
            l *= 0.125f;
            float mx = l;
            #pragma unroll
            for (int o = 8; o; o >>= 1) mx = fmaxf(mx, __shfl_xor_sync(0xffffffffu, mx, o));
            float ex = expf(l - mx);
            float sme = ex;
            #pragma unroll
            for (int o = 8; o; o >>= 1) sme += __shfl_xor_sync(0xffffffffu, sme, o);
            prob[s][u] = ex / sme;
        }
        __syncthreads();
        float at[4];
        #pragma unroll
        for (int r = 0; r < 4; r++) {
            int s = s0 + 4 * r;
            float a = 0.f;
            #pragma unroll
            for (int u = 0; u < 16; u++) a += prob[s][u] * vi[u][d];
            at[r] = a;
        }
        if (it == 0) {
            #pragma unroll
            for (int r = 0; r < 4; r++) {
                int s = s0 + 4 * r;
                ip[s][d] = at[r];
                qc[s][d] += at[r];
            }
        } else if (it == 1) {
            #pragma unroll
            for (int r = 0; r < 4; r++) {
                int s = s0 + 4 * r;
                diffacc += fabsf(at[r] - ip[s][d]);
                qc[s][d] += at[r];
                g_A1[base + (size_t)s * 1024] = at[r];
            }
        } else {
            #pragma unroll
            for (int r = 0; r < 4; r++) {
                int s = s0 + 4 * r;
                g_A2[base + (size_t)s * 1024] = at[r];
            }
        }
        __syncthreads();
    }

    // block reduce + one atomic
    #pragma unroll
    for (int o = 16; o; o >>= 1) diffacc += __shfl_xor_sync(0xffffffffu, diffacc, o);
    if ((t & 31) == 0) red[t >> 5] = diffacc;
    __syncthreads();
    if (t < 8) {
        float v = red[t];
        #pragma unroll
        for (int o = 4; o; o >>= 1) v += __shfl_xor_sync(0xffu, v, o);
        if (t == 0) atomicAdd(&g_diffsum, v);
    }
}

// ---------------------------------------------------------------------------
// Kernel 4: output projection as tf32 tensor-core GEMM; selects iter1/iter2;
// scatters rows to out[(b*CTX + s)*1024 + c] and adds ob. 64 blocks.
// ---------------------------------------------------------------------------
__global__ void __launch_bounds__(256) proj_tc(
    const float* __restrict__ ow, const float* __restrict__ ob,
    float* __restrict__ out) {
    const float diff = g_diffsum * (1.0f / 33554432.0f);
    const float* IN = (diff < (0.01f + 0.1f * diff)) ? g_A1 : g_A2;

    const int t = threadIdx.x;
    const int r0 = (blockIdx.x >> 4) * 32;
    const int c0 = (blockIdx.x & 15) * 64;

    __shared__ float As[32][36];
    __shared__ float Ws[64][36];

    const int w = t >> 5, l = t & 31;
    const int mr  = (w >> 2) * 16;
    const int nc  = (w & 3) * 16;
    const int g   = l >> 2, tig = l & 3;
    const int lrow = t >> 3, lk = (t & 7) * 4;

    float acc[2][4] = {{0,0,0,0},{0,0,0,0}};

    for (int k0 = 0; k0 < 1024; k0 += 32) {
        float4 xa = *(const float4*)(IN + (size_t)(r0 + lrow) * 1024 + k0 + lk);
        float4 w0 = *(const float4*)(ow + (size_t)(c0 + lrow) * 1024 + k0 + lk);
        float4 w1 = *(const float4*)(ow + (size_t)(c0 + 32 + lrow) * 1024 + k0 + lk);
        __syncthreads();
        *(float4*)&As[lrow][lk]      = xa;
        *(float4*)&Ws[lrow][lk]      = w0;
        *(float4*)&Ws[32 + lrow][lk] = w1;
        __syncthreads();
        #pragma unroll
        for (int ks = 0; ks < 4; ks++) {
            const int kb = ks * 8;
            unsigned a0 = f2tf(As[mr + g][kb + tig]);
            unsigned a1 = f2tf(As[mr + g + 8][kb + tig]);
            unsigned a2 = f2tf(As[mr + g][kb + tig + 4]);
            unsigned a3 = f2tf(As[mr + g + 8][kb + tig + 4]);
            #pragma unroll
            for (int j = 0; j < 2; j++) {
                unsigned b0 = f2tf(Ws[nc + j * 8 + g][kb + tig]);
                unsigned b1 = f2tf(Ws[nc + j * 8 + g][kb + tig + 4]);
                mma_tf32(acc[j], a0, a1, a2, a3, b0, b1);
            }
        }
    }
    const int row0 = r0 + mr + g, row1 = row0 + 8;
    const size_t o0 = ((size_t)(row0 >> 4) * CTXL + (row0 & 15)) * 1024;
    const size_t o1 = ((size_t)(row1 >> 4) * CTXL + (row1 & 15)) * 1024;
    #pragma unroll
    for (int j = 0; j < 2; j++) {
        const int colb = c0 + nc + j * 8 + 2 * tig;
        const float b0v = ob[colb], b1v = ob[colb + 1];
        out[o0 + colb]     = acc[j][0] + b0v;
        out[o0 + colb + 1] = acc[j][1] + b1v;
        out[o1 + colb]     = acc[j][2] + b0v;
        out[o1 + colb + 1] = acc[j][3] + b1v;
    }
}

// ---------------------------------------------------------------------------
extern "C" void kernel_launch(void* const* d_in, const int* in_sizes, int n_in,
                              void* d_out, int out_size) {
    const float* x   = (const float*)d_in[0];
    const float* qw  = (const float*)d_in[1];
    const float* qb  = (const float*)d_in[2];
    const float* kw  = (const float*)d_in[3];
    const float* vw  = (const float*)d_in[4];
    const float* vb  = (const float*)d_in[5];
    const float* ow  = (const float*)d_in[6];
    const float* ob  = (const float*)d_in[7];
    const float* lna = (const float*)d_in[8];
    const float* lnb = (const float*)d_in[9];
    const float* lnc = (const float*)d_in[10];
    const float* lnd = (const float*)d_in[11];
    const float* lqw = (const float*)d_in[12];
    const float* lqb = (const float*)d_in[13];
    const float* lkw = (const float*)d_in[14];
    const float* lkb = (const float*)d_in[15];
    const float* lvw = (const float*)d_in[16];
    const float* lvb = (const float*)d_in[17];
    float* out = (float*)d_out;

    const int attn_smem = (3 * 64 * 65 + 7 * 16 * 65 + 256 + 40) * 4;
    cudaFuncSetAttribute(attn_kernel, cudaFuncAttributeMaxDynamicSharedMemorySize,
                         attn_smem);

    ln_kernel<<<128, 256>>>(x, lna, lnb);
    // 192 GEMM blocks + 160 fill blocks (first half of out)
    qkv_tc<<<352, 256>>>(qw, qb, kw, vw, vb, (float4*)out, (const float4*)ob);
    // 128 attn blocks + 224 fill blocks (second half of out)
    attn_kernel<<<352, 256, attn_smem>>>(lnc, lnd, lqw, lqb, lkw, lkb, lvw, lvb,
                                         (float4*)out, (const float4*)ob);
    proj_tc<<<64, 256>>>(ow, ob, out);
}

// round 8
// speedup vs baseline: 4.0824x; 1.5831x over previous
#include <cuda_runtime.h>

#define NB    8
#define NH    16
#define HDIM  64
#define NDIMS 1024
#define CTXL  4096

// Scratch (__device__ globals: allocation-free rule)
__device__ __align__(16) float g_xa[128 * 1024];
__device__ __align__(16) float g_xb[128 * 1024];
__device__ __align__(16) float g_q [128 * 1024];
__device__ __align__(16) float g_k [128 * 1024];
__device__ __align__(16) float g_v [128 * 1024];
__device__ __align__(16) float g_A1[128 * 1024];
__device__ __align__(16) float g_A2[128 * 1024];
__device__ float g_diffsum;

// ---------------------------------------------------------------------------
// tf32 helpers
// ---------------------------------------------------------------------------
__device__ __forceinline__ unsigned f2tf(float f) {
    unsigned r;
    asm("cvt.rna.tf32.f32 %0, %1;" : "=r"(r) : "f"(f));
    return r;
}
__device__ __forceinline__ void mma_tf32(float* c, unsigned a0, unsigned a1,
                                         unsigned a2, unsigned a3,
                                         unsigned b0, unsigned b1) {
    asm("mma.sync.aligned.m16n8k8.row.col.f32.tf32.tf32.f32 "
        "{%0,%1,%2,%3},{%4,%5,%6,%7},{%8,%9},{%0,%1,%2,%3};"
        : "+f"(c[0]), "+f"(c[1]), "+f"(c[2]), "+f"(c[3])
        : "r"(a0), "r"(a1), "r"(a2), "r"(a3), "r"(b0), "r"(b1));
}

// ---------------------------------------------------------------------------
// Kernel 1: LayerNorm of 128 active rows -> g_xa (lna), g_xb (lnb); reset diff.
// ---------------------------------------------------------------------------
__global__ void __launch_bounds__(256) ln_kernel(const float* __restrict__ x,
                                                 const float* __restrict__ lna,
                                                 const float* __restrict__ lnb) {
    if (blockIdx.x == 0 && threadIdx.x == 0) g_diffsum = 0.0f;
    const int row = blockIdx.x;                 // 0..127 = b*16+s
    const int b = row >> 4, s = row & 15;
    const int t = threadIdx.x;
    const float4* xr = (const float4*)(x + ((size_t)b * CTXL + s) * NDIMS);
    float4 v = xr[t];
    float sum = v.x + v.y + v.z + v.w;
    float sq  = v.x*v.x + v.y*v.y + v.z*v.z + v.w*v.w;
    #pragma unroll
    for (int o = 16; o; o >>= 1) {
        sum += __shfl_xor_sync(0xffffffffu, sum, o);
        sq  += __shfl_xor_sync(0xffffffffu, sq,  o);
    }
    __shared__ float s1[8], s2[8], sm_m, sm_r;
    if ((t & 31) == 0) { s1[t >> 5] = sum; s2[t >> 5] = sq; }
    __syncthreads();
    if (t == 0) {
        float a = 0.f, q = 0.f;
        #pragma unroll
        for (int i = 0; i < 8; i++) { a += s1[i]; q += s2[i]; }
        float m   = a * (1.f / 1024.f);
        float var = q * (1.f / 1024.f) - m * m;
        sm_m = m; sm_r = rsqrtf(var + 1e-5f);
    }
    __syncthreads();
    const float m = sm_m, rs = sm_r;
    float4 la = ((const float4*)lna)[t];
    float4 lb = ((const float4*)lnb)[t];
    float4 xa, xb;
    float c0 = (v.x - m) * rs, c1 = (v.y - m) * rs, c2 = (v.z - m) * rs, c3 = (v.w - m) * rs;
    xa.x = c0 * la.x; xa.y = c1 * la.y; xa.z = c2 * la.z; xa.w = c3 * la.w;
    xb.x = c0 * lb.x; xb.y = c1 * lb.y; xb.z = c2 * lb.z; xb.w = c3 * lb.w;
    ((float4*)g_xa)[row * 256 + t] = xa;
    ((float4*)g_xb)[row * 256 + t] = xb;
}

// ---------------------------------------------------------------------------
// Kernel 2: q/k/v tf32 GEMM (K-tile 64, register prefetch) + fill [0, 3670016).
// GEMM blocks 0..191 (mat=bid/64, 32x64 tile); fill blocks 192..351.
// ---------------------------------------------------------------------------
__global__ void __launch_bounds__(256) qkv_tc(
    const float* __restrict__ qw, const float* __restrict__ qb,
    const float* __restrict__ kw,
    const float* __restrict__ vw, const float* __restrict__ vb,
    float4* __restrict__ out4, const float4* __restrict__ ob4) {
    const int t = threadIdx.x;
    const int bid = blockIdx.x;
    if (bid >= 192) {
        const float4 v = ob4[t];
        const unsigned stride = 160u * 256u;
        for (unsigned i = (unsigned)(bid - 192) * 256u + t; i < 3670016u; i += stride)
            out4[i] = v;
        return;
    }
    const int mat = bid >> 6;
    const int sub = bid & 63;
    const int r0 = (sub >> 4) * 32;
    const int c0 = (sub & 15) * 64;
    const float* IN   = (mat == 0) ? g_xa : g_xb;
    const float* W    = (mat == 0) ? qw : (mat == 1) ? kw : vw;
    const float* bias = (mat == 0) ? qb : (mat == 1) ? (const float*)0 : vb;
    float* OUT        = (mat == 0) ? g_q : (mat == 1) ? g_k : g_v;

    __shared__ float As[32][68];
    __shared__ float Ws[64][68];

    const int w = t >> 5, l = t & 31;
    const int mr  = (w >> 2) * 16;
    const int nc_ = (w & 3) * 16;
    const int g   = l >> 2, tig = l & 3;
    const int lr  = t >> 3, lk = (t & 7) * 8;

    float acc[2][4] = {{0,0,0,0},{0,0,0,0}};

    const float* Ap  = IN + (size_t)(r0 + lr) * 1024 + lk;
    const float* Wp0 = W  + (size_t)(c0 + lr) * 1024 + lk;
    const float* Wp1 = W  + (size_t)(c0 + 32 + lr) * 1024 + lk;
    float4 pa0 = *(const float4*)Ap,        pa1 = *(const float4*)(Ap + 4);
    float4 pw0 = *(const float4*)Wp0,       pw1 = *(const float4*)(Wp0 + 4);
    float4 pw2 = *(const float4*)Wp1,       pw3 = *(const float4*)(Wp1 + 4);

    for (int k0 = 0; k0 < 1024; k0 += 64) {
        __syncthreads();
        *(float4*)&As[lr][lk]          = pa0; *(float4*)&As[lr][lk + 4]      = pa1;
        *(float4*)&Ws[lr][lk]          = pw0; *(float4*)&Ws[lr][lk + 4]      = pw1;
        *(float4*)&Ws[lr + 32][lk]     = pw2; *(float4*)&Ws[lr + 32][lk + 4] = pw3;
        __syncthreads();
        if (k0 + 64 < 1024) {   // prefetch next tile (overlaps with MMA below)
            pa0 = *(const float4*)(Ap  + k0 + 64); pa1 = *(const float4*)(Ap  + k0 + 68);
            pw0 = *(const float4*)(Wp0 + k0 + 64); pw1 = *(const float4*)(Wp0 + k0 + 68);
            pw2 = *(const float4*)(Wp1 + k0 + 64); pw3 = *(const float4*)(Wp1 + k0 + 68);
        }
        #pragma unroll
        for (int ks = 0; ks < 8; ks++) {
            const int kb = ks * 8;
            unsigned a0 = f2tf(As[mr + g][kb + tig]);
            unsigned a1 = f2tf(As[mr + g + 8][kb + tig]);
            unsigned a2 = f2tf(As[mr + g][kb + tig + 4]);
            unsigned a3 = f2tf(As[mr + g + 8][kb + tig + 4]);
            #pragma unroll
            for (int j = 0; j < 2; j++) {
                unsigned b0 = f2tf(Ws[nc_ + j * 8 + g][kb + tig]);
                unsigned b1 = f2tf(Ws[nc_ + j * 8 + g][kb + tig + 4]);
                mma_tf32(acc[j], a0, a1, a2, a3, b0, b1);
            }
        }
    }
    const int row0 = r0 + mr + g, row1 = row0 + 8;
    #pragma unroll
    for (int j = 0; j < 2; j++) {
        const int colb = c0 + nc_ + j * 8 + 2 * tig;
        float b0v = 0.f, b1v = 0.f;
        if (bias) { b0v = bias[colb]; b1v = bias[colb + 1]; }
        OUT[(size_t)row0 * 1024 + colb]     = acc[j][0] + b0v;
        OUT[(size_t)row0 * 1024 + colb + 1] = acc[j][1] + b1v;
        OUT[(size_t)row1 * 1024 + colb]     = acc[j][2] + b0v;
        OUT[(size_t)row1 * 1024 + colb + 1] = acc[j][3] + b1v;
    }
}

// ---------------------------------------------------------------------------
// Kernel 3: attention. Blocks 0..127 compute (sync-free iteration loop, each
// warp owns 2 query rows); blocks 128..319 fill [3670016, 6815744) plus the
// b6/b7 s<16 slices. Dynamic smem ~75KB.
// ---------------------------------------------------------------------------
__global__ void __launch_bounds__(256) attn_kernel(
    const float* __restrict__ lnc, const float* __restrict__ lnd,
    const float* __restrict__ lqw, const float* __restrict__ lqb,
    const float* __restrict__ lkw, const float* __restrict__ lkb,
    const float* __restrict__ lvw, const float* __restrict__ lvb,
    float4* __restrict__ out4, const float4* __restrict__ ob4) {
    const int t = threadIdx.x;
    if (blockIdx.x >= 128) {
        const int fb = blockIdx.x - 128;       // 0..191
        const float4 v = ob4[t];
        const unsigned stride = 192u * 256u;
        for (unsigned i = 3670016u + (unsigned)fb * 256u + t; i < 6815744u; i += stride)
            out4[i] = v;
        if (fb < 16) out4[7340032u + (unsigned)fb * 256u + t] = v;  // b7 s<16 slice
        return;
    }
    extern __shared__ float sm[];
    float (*wq)[65] = (float(*)[65])sm;                  // 64x65
    float (*wk)[65] = (float(*)[65])(sm + 64 * 65);
    float (*wv)[65] = (float(*)[65])(sm + 2 * 64 * 65);
    float (*kt)[65] = (float(*)[65])(sm + 3 * 64 * 65);  // 16x65 each below
    float (*vt)[65] = kt + 16;
    float (*kn)[65] = vt + 16;
    float (*vi)[65] = kn + 16;
    float (*qc)[65] = vi + 16;
    float (*qn)[65] = qc + 16;
    float* rm  = (float*)(qn + 16);                      // 16
    float* rr  = rm + 16;                                // 16
    float* red = rr + 16;                                // 8

    const int b = blockIdx.x >> 4, h = blockIdx.x & 15;
    const int w = t >> 5, lane = t & 31;

    // stage 64x64 weights (coalesced loads, conflict-free padded smem)
    {
        const int rw = t >> 4, col = (t & 15) * 4;
        #pragma unroll
        for (int p = 0; p < 4; p++) {
            int row = p * 16 + rw;
            float4 a = *(const float4*)(lqw + row * 64 + col);
            wq[row][col] = a.x; wq[row][col+1] = a.y; wq[row][col+2] = a.z; wq[row][col+3] = a.w;
            float4 c = *(const float4*)(lkw + row * 64 + col);
            wk[row][col] = c.x; wk[row][col+1] = c.y; wk[row][col+2] = c.z; wk[row][col+3] = c.w;
            float4 e = *(const float4*)(lvw + row * 64 + col);
            wv[row][col] = e.x; wv[row][col+1] = e.y; wv[row][col+2] = e.z; wv[row][col+3] = e.w;
        }
    }
    const int d = t & 63, s0 = t >> 6;
    const size_t base = (size_t)(b * 16) * 1024 + h * 64;
    #pragma unroll
    for (int r = 0; r < 4; r++) {
        int s = s0 + 4 * r;
        qc[s][d] = g_q[base + (size_t)s * 1024 + d];
        kt[s][d] = g_k[base + (size_t)s * 1024 + d];
        vt[s][d] = g_v[base + (size_t)s * 1024 + d];
    }
    __syncthreads();

    // kn_pre = k @ lkw.T + lkb, vi = v @ lvw.T + lvb (block-wide, once)
    {
        float akn[4], avi[4];
        const float bk = lkb[d], bv = lvb[d];
        #pragma unroll
        for (int r = 0; r < 4; r++) { akn[r] = bk; avi[r] = bv; }
        for (int e = 0; e < 64; e++) {
            float wke = wk[d][e], wve = wv[d][e];
            #pragma unroll
            for (int r = 0; r < 4; r++) {
                int s = s0 + 4 * r;
                akn[r] += kt[s][e] * wke;
                avi[r] += vt[s][e] * wve;
            }
        }
        #pragma unroll
        for (int r = 0; r < 4; r++) { int s = s0 + 4 * r; kn[s][d] = akn[r]; vi[s][d] = avi[r]; }
    }
    __syncthreads();
    {   // LN over 64-dim kn rows
        const int s = t >> 4, l16 = t & 15;
        float v0 = kn[s][l16], v1 = kn[s][l16+16], v2 = kn[s][l16+32], v3 = kn[s][l16+48];
        float sum = v0+v1+v2+v3, sq = v0*v0+v1*v1+v2*v2+v3*v3;
        #pragma unroll
        for (int o = 8; o; o >>= 1) {
            sum += __shfl_xor_sync(0xffffffffu, sum, o);
            sq  += __shfl_xor_sync(0xffffffffu, sq,  o);
        }
        if (l16 == 0) {
            float m = sum * (1.f/64.f), var = sq * (1.f/64.f) - m*m;
            rm[s] = m; rr[s] = rsqrtf(var + 1e-5f);
        }
    }
    __syncthreads();
    {
        const float lndd = lnd[d];
        #pragma unroll
        for (int r = 0; r < 4; r++) {
            int s = s0 + 4 * r;
            kn[s][d] = (kn[s][d] - rm[s]) * rr[s] * lndd;
        }
    }
    __syncthreads();

    // ---- sync-free iteration loop: warp w owns rows sA=2w, sB=2w+1 ----
    const int d0 = lane, d1 = lane + 32;
    const int sA = 2 * w, sB = sA + 1;
    const float lqb0 = lqb[d0], lqb1 = lqb[d1];
    const float lnc0 = lnc[d0], lnc1 = lnc[d1];
    const size_t baseA = base + (size_t)sA * 1024;
    const size_t baseB = base + (size_t)sB * 1024;

    float diffacc = 0.f;
    float ipA0 = 0.f, ipA1 = 0.f, ipB0 = 0.f, ipB1 = 0.f;

    #pragma unroll
    for (int it = 0; it < 3; it++) {
        // qn_pre rows
        float aA0 = lqb0, aA1 = lqb1, aB0 = lqb0, aB1 = lqb1;
        #pragma unroll 16
        for (int e = 0; e < 64; e++) {
            float ca = qc[sA][e], cb = qc[sB][e];
            float w0 = wq[d0][e], w1 = wq[d1][e];
            aA0 += ca * w0; aA1 += ca * w1;
            aB0 += cb * w0; aB1 += cb * w1;
        }
        // LN over 64 per row (full-warp butterfly, 2 elems/lane)
        float sumA = aA0 + aA1, sqA = aA0*aA0 + aA1*aA1;
        float sumB = aB0 + aB1, sqB = aB0*aB0 + aB1*aB1;
        #pragma unroll
        for (int o = 16; o; o >>= 1) {
            sumA += __shfl_xor_sync(0xffffffffu, sumA, o);
            sqA  += __shfl_xor_sync(0xffffffffu, sqA,  o);
            sumB += __shfl_xor_sync(0xffffffffu, sumB, o);
            sqB  += __shfl_xor_sync(0xffffffffu, sqB,  o);
        }
        float mA = sumA * (1.f/64.f), rA = rsqrtf(sqA * (1.f/64.f) - mA*mA + 1e-5f);
        float mB = sumB * (1.f/64.f), rB = rsqrtf(sqB * (1.f/64.f) - mB*mB + 1e-5f);
        qn[sA][d0] = (aA0 - mA) * rA * lnc0; qn[sA][d1] = (aA1 - mA) * rA * lnc1;
        qn[sB][d0] = (aB0 - mB) * rB * lnc0; qn[sB][d1] = (aB1 - mB) * rB * lnc1;
        __syncwarp();

        // logits: lanes 0-15 row sA, lanes 16-31 row sB; u = lane&15
        const int srow = (lane < 16) ? sA : sB;
        const int u = lane & 15;
        float lg = 0.f;
        #pragma unroll 16
        for (int e = 0; e < 64; e++) lg += qn[srow][e] * kn[u][e];
        lg *= 0.125f;
        float mx = lg;
        #pragma unroll
        for (int o = 8; o; o >>= 1) mx = fmaxf(mx, __shfl_xor_sync(0xffffffffu, mx, o));
        float ex = expf(lg - mx);
        float se = ex;
        #pragma unroll
        for (int o = 8; o; o >>= 1) se += __shfl_xor_sync(0xffffffffu, se, o);
        float p = ex / se;

        // attn = P @ vi
        float oA0 = 0.f, oA1 = 0.f, oB0 = 0.f, oB1 = 0.f;
        #pragma unroll
        for (int uu = 0; uu < 16; uu++) {
            float pA = __shfl_sync(0xffffffffu, p, uu);
            float pB = __shfl_sync(0xffffffffu, p, uu + 16);
            float v0 = vi[uu][d0], v1 = vi[uu][d1];
            oA0 += pA * v0; oA1 += pA * v1;
            oB0 += pB * v0; oB1 += pB * v1;
        }

        if (it == 0) {
            ipA0 = oA0; ipA1 = oA1; ipB0 = oB0; ipB1 = oB1;
            qc[sA][d0] += oA0; qc[sA][d1] += oA1;
            qc[sB][d0] += oB0; qc[sB][d1] += oB1;
        } else if (it == 1) {
            diffacc += fabsf(oA0 - ipA0) + fabsf(oA1 - ipA1)
                     + fabsf(oB0 - ipB0) + fabsf(oB1 - ipB1);
            qc[sA][d0] += oA0; qc[sA][d1] += oA1;
            qc[sB][d0] += oB0; qc[sB][d1] += oB1;
            g_A1[baseA + d0] = oA0; g_A1[baseA + d1] = oA1;
            g_A1[baseB + d0] = oB0; g_A1[baseB + d1] = oB1;
        } else {
            g_A2[baseA + d0] = oA0; g_A2[baseA + d1] = oA1;
            g_A2[baseB + d0] = oB0; g_A2[baseB + d1] = oB1;
        }
        __syncwarp();
    }

    // block reduce diff + one atomic
    #pragma unroll
    for (int o = 16; o; o >>= 1) diffacc += __shfl_xor_sync(0xffffffffu, diffacc, o);
    if (lane == 0) red[w] = diffacc;
    __syncthreads();
    if (t < 8) {
        float v = red[t];
        #pragma unroll
        for (int o = 4; o; o >>= 1) v += __shfl_xor_sync(0xffu, v, o);
        if (t == 0) atomicAdd(&g_diffsum, v);
    }
}

// ---------------------------------------------------------------------------
// Kernel 4: output projection, split-K x4 tf32 GEMM (256 blocks) atomicAdd
// onto ob-prefilled rows, + fill [6815744, 8388608) \ b7-s<16 (96 blocks).
// ---------------------------------------------------------------------------
__global__ void __launch_bounds__(256) proj_tc(
    const float* __restrict__ ow, float* __restrict__ out,
    float4* __restrict__ out4, const float4* __restrict__ ob4) {
    const int t = threadIdx.x;
    const int bid = blockIdx.x;
    if (bid >= 256) {
        const int fb = bid - 256;              // 0..95
        const float4 v = ob4[t];
        const unsigned stride = 96u * 256u;
        for (unsigned i = 6815744u + (unsigned)fb * 256u + t; i < 8388608u; i += stride)
            if (i < 7340032u || i >= 7344128u)   // skip b7 s<16 (atomic targets)
                out4[i] = v;
        return;
    }
    const float diff = g_diffsum * (1.0f / 33554432.0f);
    const float* IN = (diff < (0.01f + 0.1f * diff)) ? g_A1 : g_A2;

    const int ksl = bid >> 6;                  // k-slice 0..3
    const int sub = bid & 63;
    const int r0 = (sub >> 4) * 32;
    const int c0 = (sub & 15) * 64;
    const int kbase = ksl * 256;

    __shared__ float As[32][68];
    __shared__ float Ws[64][68];

    const int w = t >> 5, l = t & 31;
    const int mr  = (w >> 2) * 16;
    const int nc_ = (w & 3) * 16;
    const int g   = l >> 2, tig = l & 3;
    const int lr  = t >> 3, lk = (t & 7) * 8;

    float acc[2][4] = {{0,0,0,0},{0,0,0,0}};

    const float* Ap  = IN + (size_t)(r0 + lr) * 1024 + kbase + lk;
    const float* Wp0 = ow + (size_t)(c0 + lr) * 1024 + kbase + lk;
    const float* Wp1 = ow + (size_t)(c0 + 32 + lr) * 1024 + kbase + lk;
    float4 pa0 = *(const float4*)Ap,  pa1 = *(const float4*)(Ap + 4);
    float4 pw0 = *(const float4*)Wp0, pw1 = *(const float4*)(Wp0 + 4);
    float4 pw2 = *(const float4*)Wp1, pw3 = *(const float4*)(Wp1 + 4);

    for (int k0 = 0; k0 < 256; k0 += 64) {
        __syncthreads();
        *(float4*)&As[lr][lk]          = pa0; *(float4*)&As[lr][lk + 4]      = pa1;
        *(float4*)&Ws[lr][lk]          = pw0; *(float4*)&Ws[lr][lk + 4]      = pw1;
        *(float4*)&Ws[lr + 32][lk]     = pw2; *(float4*)&Ws[lr + 32][lk + 4] = pw3;
        __syncthreads();
        if (k0 + 64 < 256) {
            pa0 = *(const float4*)(Ap  + k0 + 64); pa1 = *(const float4*)(Ap  + k0 + 68);
            pw0 = *(const float4*)(Wp0 + k0 + 64); pw1 = *(const float4*)(Wp0 + k0 + 68);
            pw2 = *(const float4*)(Wp1 + k0 + 64); pw3 = *(const float4*)(Wp1 + k0 + 68);
        }
        #pragma unroll
        for (int ks = 0; ks < 8; ks++) {
            const int kb = ks * 8;
            unsigned a0 = f2tf(As[mr + g][kb + tig]);
            unsigned a1 = f2tf(As[mr + g + 8][kb + tig]);
            unsigned a2 = f2tf(As[mr + g][kb + tig + 4]);
            unsigned a3 = f2tf(As[mr + g + 8][kb + tig + 4]);
            #pragma unroll
            for (int j = 0; j < 2; j++) {
                unsigned b0 = f2tf(Ws[nc_ + j * 8 + g][kb + tig]);
                unsigned b1 = f2tf(Ws[nc_ + j * 8 + g][kb + tig + 4]);
                mma_tf32(acc[j], a0, a1, a2, a3, b0, b1);
            }
        }
    }
    const int row0 = r0 + mr + g, row1 = row0 + 8;
    const size_t o0 = ((size_t)(row0 >> 4) * CTXL + (row0 & 15)) * 1024;
    const size_t o1 = ((size_t)(row1 >> 4) * CTXL + (row1 & 15)) * 1024;
    #pragma unroll
    for (int j = 0; j < 2; j++) {
        const int colb = c0 + nc_ + j * 8 + 2 * tig;
        atomicAdd(&out[o0 + colb],     acc[j][0]);
        atomicAdd(&out[o0 + colb + 1], acc[j][1]);
        atomicAdd(&out[o1 + colb],     acc[j][2]);
        atomicAdd(&out[o1 + colb + 1], acc[j][3]);
    }
}

// ---------------------------------------------------------------------------
extern "C" void kernel_launch(void* const* d_in, const int* in_sizes, int n_in,
                              void* d_out, int out_size) {
    const float* x   = (const float*)d_in[0];
    const float* qw  = (const float*)d_in[1];
    const float* qb  = (const float*)d_in[2];
    const float* kw  = (const float*)d_in[3];
    const float* vw  = (const float*)d_in[4];
    const float* vb  = (const float*)d_in[5];
    const float* ow  = (const float*)d_in[6];
    const float* ob  = (const float*)d_in[7];
    const float* lna = (const float*)d_in[8];
    const float* lnb = (const float*)d_in[9];
    const float* lnc = (const float*)d_in[10];
    const float* lnd = (const float*)d_in[11];
    const float* lqw = (const float*)d_in[12];
    const float* lqb = (const float*)d_in[13];
    const float* lkw = (const float*)d_in[14];
    const float* lkb = (const float*)d_in[15];
    const float* lvw = (const float*)d_in[16];
    const float* lvb = (const float*)d_in[17];
    float* out = (float*)d_out;

    // attn dynamic smem: 3*64*65 + 6*16*65 + 40 floats
    const int attn_smem = (3 * 64 * 65 + 6 * 16 * 65 + 40) * 4;
    cudaFuncSetAttribute(attn_kernel, cudaFuncAttributeMaxDynamicSharedMemorySize,
                         attn_smem);

    ln_kernel<<<128, 256>>>(x, lna, lnb);
    // 192 GEMM + 160 fill blocks (fill [0, 3670016) float4s, incl. b0..b3 s<16)
    qkv_tc<<<352, 256>>>(qw, qb, kw, vw, vb, (float4*)out, (const float4*)ob);
    // 128 attn + 192 fill blocks (fill [3670016, 6815744) + b7 s<16 slice)
    attn_kernel<<<320, 256, attn_smem>>>(lnc, lnd, lqw, lqb, lkw, lkb, lvw, lvb,
                                         (float4*)out, (const float4*)ob);
    // 256 split-K GEMM (atomicAdd onto ob-prefilled rows) + 96 fill blocks
    proj_tc<<<352, 256>>>(ow, out, (float4*)out, (const float4*)ob);
}